// round 13
// baseline (speedup 1.0000x reference)
#include <cuda_runtime.h>
#include <cstdint>

#define NN 10000
#define DD 128
#define MAXE 256             // max nonzeros/row (mean ~31, extreme tail ~70)
#define CHUNK4 125           // float4 per chunk (20 * 125 = 2500 = row)
#define CHUNKB (CHUNK4 * 16) // 2000 bytes
#define NCHUNK 20
#define STAGES 4

// ---- mbarrier / bulk-async helpers ----------------------------------------
__device__ __forceinline__ uint32_t smem_u32(const void* p) {
    return (uint32_t)__cvta_generic_to_shared(p);
}
__device__ __forceinline__ void mbar_init(uint32_t addr, uint32_t cnt) {
    asm volatile("mbarrier.init.shared.b64 [%0], %1;" :: "r"(addr), "r"(cnt) : "memory");
}
__device__ __forceinline__ void mbar_expect_tx(uint32_t addr, uint32_t bytes) {
    asm volatile("mbarrier.arrive.expect_tx.shared.b64 _, [%0], %1;"
                 :: "r"(addr), "r"(bytes) : "memory");
}
__device__ __forceinline__ void mbar_arrive(uint32_t addr) {
    asm volatile("mbarrier.arrive.shared.b64 _, [%0];" :: "r"(addr) : "memory");
}
__device__ __forceinline__ void mbar_wait(uint32_t addr, uint32_t parity) {
    asm volatile(
        "{\n\t"
        ".reg .pred P;\n\t"
        "LAB_WAIT%=:\n\t"
        "mbarrier.try_wait.parity.shared.b64 P, [%0], %1, 0x989680;\n\t"
        "@P bra LAB_DONE%=;\n\t"
        "bra LAB_WAIT%=;\n\t"
        "LAB_DONE%=:\n\t"
        "}"
        :: "r"(addr), "r"(parity) : "memory");
}
__device__ __forceinline__ void bulk_g2s(uint32_t dst, const void* src,
                                         uint32_t bytes, uint32_t mbar) {
    asm volatile(
        "cp.async.bulk.shared::cluster.global.mbarrier::complete_tx::bytes "
        "[%0], [%1], %2, [%3];"
        :: "r"(dst), "l"(src), "r"(bytes), "r"(mbar) : "memory");
}

// ---------------------------------------------------------------------------
// Single fused kernel: one CTA per row. 4-stage x 2KB bulk-async ring with
// full/empty mbarrier pairs (no blocking CTA barrier in the scan loop).
// Scores computed in-epilogue (no separate score kernel, no g_score array).
// ---------------------------------------------------------------------------
__global__ __launch_bounds__(128, 16) void attn_kernel(
    const float* __restrict__ inputs,
    const float* __restrict__ adj,
    const float* __restrict__ Hv,
    float* __restrict__ out)
{
    __shared__ alignas(16) float4 s_buf[STAGES][CHUNK4];
    __shared__ alignas(16) float  s_w[MAXE];
    __shared__ alignas(16) float  s_part[4 * DD];
    __shared__ int   s_idx[MAXE];
    __shared__ alignas(8) unsigned long long s_full[STAGES];
    __shared__ alignas(8) unsigned long long s_empty[STAGES];
    __shared__ int   s_cnt;
    __shared__ float s_red[4];

    const int row  = blockIdx.x;
    const int tid  = threadIdx.x;
    const int wid  = tid >> 5;
    const int lane = tid & 31;

    const char* arow = reinterpret_cast<const char*>(adj) + (size_t)row * (NN * 4);

    if (tid == 0) {
        s_cnt = 0;
        #pragma unroll
        for (int st = 0; st < STAGES; st++) {
            mbar_init(smem_u32(&s_full[st]), 1);     // completed by TMA tx
            mbar_init(smem_u32(&s_empty[st]), 128);  // completed by all threads
        }
    }
    __syncthreads();

    // Prime all 4 stages (chunks 0..3)
    if (tid == 0) {
        #pragma unroll
        for (int st = 0; st < STAGES; st++) {
            mbar_expect_tx(smem_u32(&s_full[st]), CHUNKB);
            bulk_g2s(smem_u32(&s_buf[st][0]), arow + (size_t)st * CHUNKB,
                     CHUNKB, smem_u32(&s_full[st]));
        }
    }

    // ---- Pass 1: chunked scan, producer/consumer mbarrier pipeline ---------
    for (int c = 0; c < NCHUNK; c++) {
        const int st = c & (STAGES - 1);
        const uint32_t ph = (c >> 2) & 1;
        mbar_wait(smem_u32(&s_full[st]), ph);

        if (tid < CHUNK4) {
            float4 a = s_buf[st][tid];
            int j = c * (CHUNK4 * 4) + (tid << 2);
            if (a.x != 0.0f) { int p = atomicAdd(&s_cnt, 1); s_idx[p] = j;     s_w[p] = a.x; }
            if (a.y != 0.0f) { int p = atomicAdd(&s_cnt, 1); s_idx[p] = j + 1; s_w[p] = a.y; }
            if (a.z != 0.0f) { int p = atomicAdd(&s_cnt, 1); s_idx[p] = j + 2; s_w[p] = a.z; }
            if (a.w != 0.0f) { int p = atomicAdd(&s_cnt, 1); s_idx[p] = j + 3; s_w[p] = a.w; }
        }
        mbar_arrive(smem_u32(&s_empty[st]));   // non-blocking: done with stage st

        if (tid == 0 && c + STAGES < NCHUNK) {
            // only the refiller blocks until all 128 consumers arrived
            mbar_wait(smem_u32(&s_empty[st]), ph);
            mbar_expect_tx(smem_u32(&s_full[st]), CHUNKB);
            bulk_g2s(smem_u32(&s_buf[st][0]),
                     arow + (size_t)(c + STAGES) * CHUNKB,
                     CHUNKB, smem_u32(&s_full[st]));
        }
    }
    __syncthreads();                 // all compaction atomics/stores visible
    const int cnt = s_cnt;

    // ---- Pass 2a: logits — compute score_j = dot(inputs[j], Hv) in place ---
    // Warp w handles neighbors k = w, w+4, ... Lane-parallel dot + reduce.
    const float4* inp4 = reinterpret_cast<const float4*>(inputs);
    {
        const float4 h = reinterpret_cast<const float4*>(Hv)[lane];
        for (int k = wid; k < cnt; k += 4) {
            const int j = s_idx[k];
            float4 x = __ldg(&inp4[(size_t)j * 32 + lane]);
            float d = x.x * h.x + x.y * h.y + x.z * h.z + x.w * h.w;
            #pragma unroll
            for (int off = 16; off > 0; off >>= 1)
                d += __shfl_xor_sync(0xffffffffu, d, off);
            if (lane == 0) s_w[k] *= d;
        }
    }
    __syncthreads();

    // ---- Pass 2b: softmax --------------------------------------------------
    float m = -1e30f;
    for (int k = tid; k < cnt; k += 128) m = fmaxf(m, s_w[k]);
    #pragma unroll
    for (int off = 16; off > 0; off >>= 1)
        m = fmaxf(m, __shfl_xor_sync(0xffffffffu, m, off));
    if (lane == 0) s_red[wid] = m;
    __syncthreads();
    m = fmaxf(fmaxf(s_red[0], s_red[1]), fmaxf(s_red[2], s_red[3]));
    __syncthreads();

    float s = 0.0f;
    for (int k = tid; k < cnt; k += 128) {
        float e = __expf(s_w[k] - m);
        s_w[k] = e;
        s += e;
    }
    #pragma unroll
    for (int off = 16; off > 0; off >>= 1)
        s += __shfl_xor_sync(0xffffffffu, s, off);
    if (lane == 0) s_red[wid] = s;
    __syncthreads();
    s = s_red[0] + s_red[1] + s_red[2] + s_red[3];
    const float inv = 1.0f / s;

    // ---- Pass 3: warp-split float4 gather ----------------------------------
    float4 acc = make_float4(0.f, 0.f, 0.f, 0.f);
    int k = wid;
    for (; k + 12 < cnt; k += 16) {
        float w0 = s_w[k],      w1 = s_w[k + 4],  w2 = s_w[k + 8],  w3 = s_w[k + 12];
        int   j0 = s_idx[k],    j1 = s_idx[k + 4], j2 = s_idx[k + 8], j3 = s_idx[k + 12];
        float4 x0 = __ldg(&inp4[(size_t)j0 * 32 + lane]);
        float4 x1 = __ldg(&inp4[(size_t)j1 * 32 + lane]);
        float4 x2 = __ldg(&inp4[(size_t)j2 * 32 + lane]);
        float4 x3 = __ldg(&inp4[(size_t)j3 * 32 + lane]);
        acc.x += w0 * x0.x + w1 * x1.x + w2 * x2.x + w3 * x3.x;
        acc.y += w0 * x0.y + w1 * x1.y + w2 * x2.y + w3 * x3.y;
        acc.z += w0 * x0.z + w1 * x1.z + w2 * x2.z + w3 * x3.z;
        acc.w += w0 * x0.w + w1 * x1.w + w2 * x2.w + w3 * x3.w;
    }
    for (; k < cnt; k += 4) {
        float w0 = s_w[k];
        int   j0 = s_idx[k];
        float4 x0 = __ldg(&inp4[(size_t)j0 * 32 + lane]);
        acc.x += w0 * x0.x; acc.y += w0 * x0.y;
        acc.z += w0 * x0.z; acc.w += w0 * x0.w;
    }
    reinterpret_cast<float4*>(s_part)[wid * 32 + lane] = acc;
    __syncthreads();

    float v = (s_part[tid] + s_part[DD + tid] +
               s_part[2 * DD + tid] + s_part[3 * DD + tid]) * inv;
    out[(size_t)row * DD + tid] = v;
}

// ---------------------------------------------------------------------------
extern "C" void kernel_launch(void* const* d_in, const int* in_sizes, int n_in,
                              void* d_out, int out_size)
{
    const float* inputs = (const float*)d_in[0];  // [10000,128]
    const float* adj    = (const float*)d_in[1];  // [10000,10000]
    const float* Hv     = (const float*)d_in[2];  // [128,1]
    float* out          = (float*)d_out;          // [10000,128]

    attn_kernel<<<NN, 128>>>(inputs, adj, Hv, out);
}

// round 14
// speedup vs baseline: 1.1809x; 1.1809x over previous
#include <cuda_runtime.h>
#include <cstdint>

#define NN 10000
#define DD 128
#define MAXE 256             // max nonzeros/row (mean ~31, extreme tail ~70)
#define CHUNK4 125           // float4 per chunk (20 * 125 = 2500 = row)
#define CHUNKB (CHUNK4 * 16) // 2000 bytes
#define NCHUNK 20
#define STAGES 4
#define GRID 9472            // 4 * (148 SMs * 16 CTAs) — exact 4 waves
#define NDOUBLE (NN - GRID)  // 528 low-bid CTAs take a second row (LPT order)

__device__ float g_score[NN];

// ---- mbarrier / bulk-async helpers ----------------------------------------
__device__ __forceinline__ uint32_t smem_u32(const void* p) {
    return (uint32_t)__cvta_generic_to_shared(p);
}
__device__ __forceinline__ void mbar_init(uint32_t addr, uint32_t cnt) {
    asm volatile("mbarrier.init.shared.b64 [%0], %1;" :: "r"(addr), "r"(cnt) : "memory");
}
__device__ __forceinline__ void mbar_expect_tx(uint32_t addr, uint32_t bytes) {
    asm volatile("mbarrier.arrive.expect_tx.shared.b64 _, [%0], %1;"
                 :: "r"(addr), "r"(bytes) : "memory");
}
__device__ __forceinline__ void mbar_wait(uint32_t addr, uint32_t parity) {
    asm volatile(
        "{\n\t"
        ".reg .pred P;\n\t"
        "LAB_WAIT%=:\n\t"
        "mbarrier.try_wait.parity.shared.b64 P, [%0], %1, 0x989680;\n\t"
        "@P bra LAB_DONE%=;\n\t"
        "bra LAB_WAIT%=;\n\t"
        "LAB_DONE%=:\n\t"
        "}"
        :: "r"(addr), "r"(parity) : "memory");
}
__device__ __forceinline__ void bulk_g2s(uint32_t dst, const void* src,
                                         uint32_t bytes, uint32_t mbar) {
    asm volatile(
        "cp.async.bulk.shared::cluster.global.mbarrier::complete_tx::bytes "
        "[%0], [%1], %2, [%3];"
        :: "r"(dst), "l"(src), "r"(bytes), "r"(mbar) : "memory");
}

// ---------------------------------------------------------------------------
// Kernel 1: score[j] = dot(inputs[j,:], H_v)   — one warp per row
// ---------------------------------------------------------------------------
__global__ __launch_bounds__(128) void score_kernel(
    const float* __restrict__ inputs, const float* __restrict__ Hv)
{
    int row  = blockIdx.x * (blockDim.x >> 5) + (threadIdx.x >> 5);
    int lane = threadIdx.x & 31;
    if (row >= NN) return;
    const float4* ip = reinterpret_cast<const float4*>(inputs + (size_t)row * DD);
    const float4* hv = reinterpret_cast<const float4*>(Hv);
    float4 a = ip[lane];
    float4 h = hv[lane];
    float acc = a.x * h.x + a.y * h.y + a.z * h.z + a.w * h.w;
    #pragma unroll
    for (int off = 16; off > 0; off >>= 1)
        acc += __shfl_xor_sync(0xffffffffu, acc, off);
    if (lane == 0) g_score[row] = acc;
}

// ---------------------------------------------------------------------------
// Kernel 2: grid = exactly 4 waves; bids < NDOUBLE process 2 rows (LPT:
// long jobs launch first, work-stealing fills in) — kills the 5th-wave tail
// that pinned DRAM at ~68%. Per-row pipeline identical to the measured-best
// R12 config (4-stage x 2KB bulk-async ring, 16 CTAs/SM).
// ---------------------------------------------------------------------------
__global__ __launch_bounds__(128, 16) void attn_kernel(
    const float* __restrict__ inputs,
    const float* __restrict__ adj,
    float* __restrict__ out)
{
    __shared__ alignas(16) float4 s_buf[STAGES][CHUNK4];
    __shared__ alignas(16) float  s_w[MAXE];
    __shared__ alignas(16) float  s_part[4 * DD];
    __shared__ int   s_idx[MAXE];
    __shared__ alignas(8) unsigned long long s_bar[STAGES];
    __shared__ int   s_cnt;
    __shared__ float s_red[4];

    const int bid  = blockIdx.x;
    const int tid  = threadIdx.x;
    const int wid  = tid >> 5;
    const int lane = tid & 31;
    const int nmine = (bid < NDOUBLE) ? 2 : 1;

    const float4* inp4 = reinterpret_cast<const float4*>(inputs);

    for (int r = 0; r < nmine; r++) {
        const int row = bid + r * GRID;
        const char* arow = reinterpret_cast<const char*>(adj) + (size_t)row * (NN * 4);

        // (re)init ring — safe: previous row fully drained before we get here
        if (tid == 0) {
            s_cnt = 0;
            #pragma unroll
            for (int st = 0; st < STAGES; st++) mbar_init(smem_u32(&s_bar[st]), 1);
        }
        __syncthreads();

        // prime all 4 stages
        if (tid == 0) {
            #pragma unroll
            for (int st = 0; st < STAGES; st++) {
                mbar_expect_tx(smem_u32(&s_bar[st]), CHUNKB);
                bulk_g2s(smem_u32(&s_buf[st][0]), arow + (size_t)st * CHUNKB,
                         CHUNKB, smem_u32(&s_bar[st]));
            }
        }

        // ---- Pass 1: chunked scan from SMEM --------------------------------
        for (int c = 0; c < NCHUNK; c++) {
            const int st = c & (STAGES - 1);
            mbar_wait(smem_u32(&s_bar[st]), (c >> 2) & 1);

            const int jbase = c * (CHUNK4 * 4);
            if (tid < CHUNK4) {
                float4 a = s_buf[st][tid];
                int j = jbase + (tid << 2);
                if (a.x != 0.0f) { int p = atomicAdd(&s_cnt, 1); s_idx[p] = j;     s_w[p] = a.x; }
                if (a.y != 0.0f) { int p = atomicAdd(&s_cnt, 1); s_idx[p] = j + 1; s_w[p] = a.y; }
                if (a.z != 0.0f) { int p = atomicAdd(&s_cnt, 1); s_idx[p] = j + 2; s_w[p] = a.z; }
                if (a.w != 0.0f) { int p = atomicAdd(&s_cnt, 1); s_idx[p] = j + 3; s_w[p] = a.w; }
            }
            __syncthreads();                     // stage st fully consumed
            if (tid == 0 && c + STAGES < NCHUNK) {
                mbar_expect_tx(smem_u32(&s_bar[st]), CHUNKB);
                bulk_g2s(smem_u32(&s_buf[st][0]),
                         arow + (size_t)(c + STAGES) * CHUNKB,
                         CHUNKB, smem_u32(&s_bar[st]));
            }
        }
        const int cnt = s_cnt;

        // ---- Pass 2a: logits (parallel score gather) -----------------------
        for (int k = tid; k < cnt; k += 128)
            s_w[k] = s_w[k] * __ldg(&g_score[s_idx[k]]);
        __syncthreads();

        // ---- Pass 2b: softmax ----------------------------------------------
        float m = -1e30f;
        for (int k = tid; k < cnt; k += 128) m = fmaxf(m, s_w[k]);
        #pragma unroll
        for (int off = 16; off > 0; off >>= 1)
            m = fmaxf(m, __shfl_xor_sync(0xffffffffu, m, off));
        if (lane == 0) s_red[wid] = m;
        __syncthreads();
        m = fmaxf(fmaxf(s_red[0], s_red[1]), fmaxf(s_red[2], s_red[3]));
        __syncthreads();

        float s = 0.0f;
        for (int k = tid; k < cnt; k += 128) {
            float e = __expf(s_w[k] - m);
            s_w[k] = e;
            s += e;
        }
        #pragma unroll
        for (int off = 16; off > 0; off >>= 1)
            s += __shfl_xor_sync(0xffffffffu, s, off);
        if (lane == 0) s_red[wid] = s;
        __syncthreads();
        s = s_red[0] + s_red[1] + s_red[2] + s_red[3];
        const float inv = 1.0f / s;

        // ---- Pass 3: warp-split float4 gather ------------------------------
        float4 acc = make_float4(0.f, 0.f, 0.f, 0.f);
        int k = wid;
        for (; k + 12 < cnt; k += 16) {
            float w0 = s_w[k],      w1 = s_w[k + 4],  w2 = s_w[k + 8],  w3 = s_w[k + 12];
            int   j0 = s_idx[k],    j1 = s_idx[k + 4], j2 = s_idx[k + 8], j3 = s_idx[k + 12];
            float4 x0 = __ldg(&inp4[(size_t)j0 * 32 + lane]);
            float4 x1 = __ldg(&inp4[(size_t)j1 * 32 + lane]);
            float4 x2 = __ldg(&inp4[(size_t)j2 * 32 + lane]);
            float4 x3 = __ldg(&inp4[(size_t)j3 * 32 + lane]);
            acc.x += w0 * x0.x + w1 * x1.x + w2 * x2.x + w3 * x3.x;
            acc.y += w0 * x0.y + w1 * x1.y + w2 * x2.y + w3 * x3.y;
            acc.z += w0 * x0.z + w1 * x1.z + w2 * x2.z + w3 * x3.z;
            acc.w += w0 * x0.w + w1 * x1.w + w2 * x2.w + w3 * x3.w;
        }
        for (; k < cnt; k += 4) {
            float w0 = s_w[k];
            int   j0 = s_idx[k];
            float4 x0 = __ldg(&inp4[(size_t)j0 * 32 + lane]);
            acc.x += w0 * x0.x; acc.y += w0 * x0.y;
            acc.z += w0 * x0.z; acc.w += w0 * x0.w;
        }
        reinterpret_cast<float4*>(s_part)[wid * 32 + lane] = acc;
        __syncthreads();

        float v = (s_part[tid] + s_part[DD + tid] +
                   s_part[2 * DD + tid] + s_part[3 * DD + tid]) * inv;
        out[(size_t)row * DD + tid] = v;

        __syncthreads();                 // drain before next-row re-init
    }
}

// ---------------------------------------------------------------------------
extern "C" void kernel_launch(void* const* d_in, const int* in_sizes, int n_in,
                              void* d_out, int out_size)
{
    const float* inputs = (const float*)d_in[0];  // [10000,128]
    const float* adj    = (const float*)d_in[1];  // [10000,10000]
    const float* Hv     = (const float*)d_in[2];  // [128,1]
    float* out          = (float*)d_out;          // [10000,128]

    score_kernel<<<(NN + 3) / 4, 128>>>(inputs, Hv);
    attn_kernel<<<GRID, 128>>>(inputs, adj, out);
}

// round 15
// speedup vs baseline: 1.2123x; 1.0266x over previous
#include <cuda_runtime.h>
#include <cstdint>

#define NN 10000
#define DD 128
#define MAXE 256             // max nonzeros/row (mean ~31, extreme tail ~70)
#define CHUNK4 250           // float4 per chunk (10 * 250 = 2500 = row)
#define CHUNKB (CHUNK4 * 16) // 4000 bytes
#define NCHUNK 10
#define STAGES 4

__device__ float g_score[NN];

// ---- mbarrier / bulk-async helpers ----------------------------------------
__device__ __forceinline__ uint32_t smem_u32(const void* p) {
    return (uint32_t)__cvta_generic_to_shared(p);
}
__device__ __forceinline__ void mbar_init(uint32_t addr, uint32_t cnt) {
    asm volatile("mbarrier.init.shared.b64 [%0], %1;" :: "r"(addr), "r"(cnt) : "memory");
}
__device__ __forceinline__ void mbar_expect_tx(uint32_t addr, uint32_t bytes) {
    asm volatile("mbarrier.arrive.expect_tx.shared.b64 _, [%0], %1;"
                 :: "r"(addr), "r"(bytes) : "memory");
}
__device__ __forceinline__ void mbar_wait(uint32_t addr, uint32_t parity) {
    asm volatile(
        "{\n\t"
        ".reg .pred P;\n\t"
        "LAB_WAIT%=:\n\t"
        "mbarrier.try_wait.parity.shared.b64 P, [%0], %1, 0x989680;\n\t"
        "@P bra LAB_DONE%=;\n\t"
        "bra LAB_WAIT%=;\n\t"
        "LAB_DONE%=:\n\t"
        "}"
        :: "r"(addr), "r"(parity) : "memory");
}
__device__ __forceinline__ void bulk_g2s(uint32_t dst, const void* src,
                                         uint32_t bytes, uint32_t mbar) {
    asm volatile(
        "cp.async.bulk.shared::cluster.global.mbarrier::complete_tx::bytes "
        "[%0], [%1], %2, [%3];"
        :: "r"(dst), "l"(src), "r"(bytes), "r"(mbar) : "memory");
}

// ---------------------------------------------------------------------------
// Kernel 1: score[j] = dot(inputs[j,:], H_v)   — one warp per row
// ---------------------------------------------------------------------------
__global__ __launch_bounds__(128) void score_kernel(
    const float* __restrict__ inputs, const float* __restrict__ Hv)
{
    int row  = blockIdx.x * (blockDim.x >> 5) + (threadIdx.x >> 5);
    int lane = threadIdx.x & 31;
    if (row >= NN) return;
    const float4* ip = reinterpret_cast<const float4*>(inputs + (size_t)row * DD);
    const float4* hv = reinterpret_cast<const float4*>(Hv);
    float4 a = ip[lane];
    float4 h = hv[lane];
    float acc = a.x * h.x + a.y * h.y + a.z * h.z + a.w * h.w;
    #pragma unroll
    for (int off = 16; off > 0; off >>= 1)
        acc += __shfl_xor_sync(0xffffffffu, acc, off);
    if (lane == 0) g_score[row] = acc;
}

// ---------------------------------------------------------------------------
// Kernel 2: one CTA per row. 4-stage x 4KB bulk-async ring (timed-best R10
// config). Epilogue trimmed: logits fused into the max pass; one fewer
// barrier via split reduction slots.
// ---------------------------------------------------------------------------
__global__ __launch_bounds__(128, 11) void attn_kernel(
    const float* __restrict__ inputs,
    const float* __restrict__ adj,
    float* __restrict__ out)
{
    __shared__ alignas(16) float4 s_buf[STAGES][CHUNK4];
    __shared__ alignas(16) float  s_w[MAXE];
    __shared__ alignas(16) float  s_part[4 * DD];
    __shared__ int   s_idx[MAXE];
    __shared__ alignas(8) unsigned long long s_bar[STAGES];
    __shared__ int   s_cnt;
    __shared__ float s_red[8];          // [0..3] max partials, [4..7] sum partials

    const int row  = blockIdx.x;
    const int tid  = threadIdx.x;
    const int wid  = tid >> 5;
    const int lane = tid & 31;

    const char* arow = reinterpret_cast<const char*>(adj) + (size_t)row * (NN * 4);

    if (tid == 0) {
        s_cnt = 0;
        #pragma unroll
        for (int st = 0; st < STAGES; st++) mbar_init(smem_u32(&s_bar[st]), 1);
    }
    __syncthreads();

    // Prime all 4 stages
    if (tid == 0) {
        #pragma unroll
        for (int st = 0; st < STAGES; st++) {
            mbar_expect_tx(smem_u32(&s_bar[st]), CHUNKB);
            bulk_g2s(smem_u32(&s_buf[st][0]), arow + (size_t)st * CHUNKB,
                     CHUNKB, smem_u32(&s_bar[st]));
        }
    }

    // ---- Pass 1: chunked scan from SMEM ------------------------------------
    for (int c = 0; c < NCHUNK; c++) {
        const int st = c & (STAGES - 1);
        mbar_wait(smem_u32(&s_bar[st]), (c >> 2) & 1);

        const float4* buf = s_buf[st];
        const int jbase = c * (CHUNK4 * 4);
        #pragma unroll
        for (int u = 0; u < 2; u++) {
            const int v = tid + u * 128;
            if (v < CHUNK4) {
                float4 a = buf[v];
                int j = jbase + (v << 2);
                if (a.x != 0.0f) { int p = atomicAdd(&s_cnt, 1); s_idx[p] = j;     s_w[p] = a.x; }
                if (a.y != 0.0f) { int p = atomicAdd(&s_cnt, 1); s_idx[p] = j + 1; s_w[p] = a.y; }
                if (a.z != 0.0f) { int p = atomicAdd(&s_cnt, 1); s_idx[p] = j + 2; s_w[p] = a.z; }
                if (a.w != 0.0f) { int p = atomicAdd(&s_cnt, 1); s_idx[p] = j + 3; s_w[p] = a.w; }
            }
        }
        __syncthreads();                     // stage st fully consumed
        if (tid == 0 && c + STAGES < NCHUNK) {
            mbar_expect_tx(smem_u32(&s_bar[st]), CHUNKB);
            bulk_g2s(smem_u32(&s_buf[st][0]),
                     arow + (size_t)(c + STAGES) * CHUNKB,
                     CHUNKB, smem_u32(&s_bar[st]));
        }
    }
    const int cnt = s_cnt;

    // ---- Pass 2: fused logits + max, then exp + sum ------------------------
    float m = -1e30f;
    for (int k = tid; k < cnt; k += 128) {
        float l = s_w[k] * __ldg(&g_score[s_idx[k]]);
        s_w[k] = l;
        m = fmaxf(m, l);
    }
    #pragma unroll
    for (int off = 16; off > 0; off >>= 1)
        m = fmaxf(m, __shfl_xor_sync(0xffffffffu, m, off));
    if (lane == 0) s_red[wid] = m;
    __syncthreads();                         // logits stored + max partials visible
    m = fmaxf(fmaxf(s_red[0], s_red[1]), fmaxf(s_red[2], s_red[3]));

    float s = 0.0f;
    for (int k = tid; k < cnt; k += 128) {
        float e = __expf(s_w[k] - m);
        s_w[k] = e;
        s += e;
    }
    #pragma unroll
    for (int off = 16; off > 0; off >>= 1)
        s += __shfl_xor_sync(0xffffffffu, s, off);
    if (lane == 0) s_red[4 + wid] = s;       // disjoint slots: no barrier needed above
    __syncthreads();
    s = s_red[4] + s_red[5] + s_red[6] + s_red[7];
    const float inv = 1.0f / s;

    // ---- Pass 3: warp-split float4 gather ----------------------------------
    const float4* inp4 = reinterpret_cast<const float4*>(inputs);
    float4 acc = make_float4(0.f, 0.f, 0.f, 0.f);
    int k = wid;
    for (; k + 12 < cnt; k += 16) {
        float w0 = s_w[k],      w1 = s_w[k + 4],  w2 = s_w[k + 8],  w3 = s_w[k + 12];
        int   j0 = s_idx[k],    j1 = s_idx[k + 4], j2 = s_idx[k + 8], j3 = s_idx[k + 12];
        float4 x0 = __ldg(&inp4[(size_t)j0 * 32 + lane]);
        float4 x1 = __ldg(&inp4[(size_t)j1 * 32 + lane]);
        float4 x2 = __ldg(&inp4[(size_t)j2 * 32 + lane]);
        float4 x3 = __ldg(&inp4[(size_t)j3 * 32 + lane]);
        acc.x += w0 * x0.x + w1 * x1.x + w2 * x2.x + w3 * x3.x;
        acc.y += w0 * x0.y + w1 * x1.y + w2 * x2.y + w3 * x3.y;
        acc.z += w0 * x0.z + w1 * x1.z + w2 * x2.z + w3 * x3.z;
        acc.w += w0 * x0.w + w1 * x1.w + w2 * x2.w + w3 * x3.w;
    }
    for (; k < cnt; k += 4) {
        float w0 = s_w[k];
        int   j0 = s_idx[k];
        float4 x0 = __ldg(&inp4[(size_t)j0 * 32 + lane]);
        acc.x += w0 * x0.x; acc.y += w0 * x0.y;
        acc.z += w0 * x0.z; acc.w += w0 * x0.w;
    }
    reinterpret_cast<float4*>(s_part)[wid * 32 + lane] = acc;
    __syncthreads();

    float v = (s_part[tid] + s_part[DD + tid] +
               s_part[2 * DD + tid] + s_part[3 * DD + tid]) * inv;
    out[(size_t)row * DD + tid] = v;
}

// ---------------------------------------------------------------------------
extern "C" void kernel_launch(void* const* d_in, const int* in_sizes, int n_in,
                              void* d_out, int out_size)
{
    const float* inputs = (const float*)d_in[0];  // [10000,128]
    const float* adj    = (const float*)d_in[1];  // [10000,10000]
    const float* Hv     = (const float*)d_in[2];  // [128,1]
    float* out          = (float*)d_out;          // [10000,128]

    score_kernel<<<(NN + 3) / 4, 128>>>(inputs, Hv);
    attn_kernel<<<NN, 128>>>(inputs, adj, out);
}

// round 16
// speedup vs baseline: 1.2128x; 1.0004x over previous
#include <cuda_runtime.h>
#include <cstdint>

#define NN 10000
#define DD 128
#define MAXE 256             // max nonzeros/row (mean ~31, extreme tail ~70)
#define CHUNK4 250           // float4 per chunk (10 * 250 = 2500 = row)
#define CHUNKB (CHUNK4 * 16) // 4000 bytes
#define NCHUNK 10
#define STAGES 4

__device__ float g_score[NN];

// ---- mbarrier / bulk-async helpers ----------------------------------------
__device__ __forceinline__ uint32_t smem_u32(const void* p) {
    return (uint32_t)__cvta_generic_to_shared(p);
}
__device__ __forceinline__ void mbar_init(uint32_t addr, uint32_t cnt) {
    asm volatile("mbarrier.init.shared.b64 [%0], %1;" :: "r"(addr), "r"(cnt) : "memory");
}
__device__ __forceinline__ void mbar_expect_tx(uint32_t addr, uint32_t bytes) {
    asm volatile("mbarrier.arrive.expect_tx.shared.b64 _, [%0], %1;"
                 :: "r"(addr), "r"(bytes) : "memory");
}
__device__ __forceinline__ void mbar_wait(uint32_t addr, uint32_t parity) {
    asm volatile(
        "{\n\t"
        ".reg .pred P;\n\t"
        "LAB_WAIT%=:\n\t"
        "mbarrier.try_wait.parity.shared.b64 P, [%0], %1, 0x989680;\n\t"
        "@P bra LAB_DONE%=;\n\t"
        "bra LAB_WAIT%=;\n\t"
        "LAB_DONE%=:\n\t"
        "}"
        :: "r"(addr), "r"(parity) : "memory");
}
__device__ __forceinline__ void bulk_g2s(uint32_t dst, const void* src,
                                         uint32_t bytes, uint32_t mbar) {
    asm volatile(
        "cp.async.bulk.shared::cluster.global.mbarrier::complete_tx::bytes "
        "[%0], [%1], %2, [%3];"
        :: "r"(dst), "l"(src), "r"(bytes), "r"(mbar) : "memory");
}

// ---------------------------------------------------------------------------
// Kernel 1: score[j] = dot(inputs[j,:], H_v)   — one warp per row
// ---------------------------------------------------------------------------
__global__ __launch_bounds__(128) void score_kernel(
    const float* __restrict__ inputs, const float* __restrict__ Hv)
{
    int row  = blockIdx.x * (blockDim.x >> 5) + (threadIdx.x >> 5);
    int lane = threadIdx.x & 31;
    if (row >= NN) return;
    const float4* ip = reinterpret_cast<const float4*>(inputs + (size_t)row * DD);
    const float4* hv = reinterpret_cast<const float4*>(Hv);
    float4 a = ip[lane];
    float4 h = hv[lane];
    float acc = a.x * h.x + a.y * h.y + a.z * h.z + a.w * h.w;
    #pragma unroll
    for (int off = 16; off > 0; off >>= 1)
        acc += __shfl_xor_sync(0xffffffffu, acc, off);
    if (lane == 0) g_score[row] = acc;
}

// ---------------------------------------------------------------------------
// Kernel 2: one CTA per row. 4-stage x 4KB bulk-async ring. Scan uses an
// integer-OR test (adj >= 0, so 0x0 is the only zero encoding) + real branch
// to skip the compaction block for the ~98.8% all-zero float4s — the
// predicated ATOMS/STS pairs issue even when off, wasting issue slots.
// ---------------------------------------------------------------------------
__global__ __launch_bounds__(128, 11) void attn_kernel(
    const float* __restrict__ inputs,
    const float* __restrict__ adj,
    float* __restrict__ out)
{
    __shared__ alignas(16) float4 s_buf[STAGES][CHUNK4];
    __shared__ alignas(16) float  s_w[MAXE];
    __shared__ alignas(16) float  s_part[4 * DD];
    __shared__ int   s_idx[MAXE];
    __shared__ alignas(8) unsigned long long s_bar[STAGES];
    __shared__ int   s_cnt;
    __shared__ float s_red[8];          // [0..3] max partials, [4..7] sum partials

    const int row  = blockIdx.x;
    const int tid  = threadIdx.x;
    const int wid  = tid >> 5;
    const int lane = tid & 31;

    const char* arow = reinterpret_cast<const char*>(adj) + (size_t)row * (NN * 4);

    if (tid == 0) {
        s_cnt = 0;
        #pragma unroll
        for (int st = 0; st < STAGES; st++) mbar_init(smem_u32(&s_bar[st]), 1);
    }
    __syncthreads();

    // Prime all 4 stages
    if (tid == 0) {
        #pragma unroll
        for (int st = 0; st < STAGES; st++) {
            mbar_expect_tx(smem_u32(&s_bar[st]), CHUNKB);
            bulk_g2s(smem_u32(&s_buf[st][0]), arow + (size_t)st * CHUNKB,
                     CHUNKB, smem_u32(&s_bar[st]));
        }
    }

    // ---- Pass 1: chunked scan from SMEM ------------------------------------
    for (int c = 0; c < NCHUNK; c++) {
        const int st = c & (STAGES - 1);
        mbar_wait(smem_u32(&s_bar[st]), (c >> 2) & 1);

        const uint4* buf = reinterpret_cast<const uint4*>(s_buf[st]);
        const int jbase = c * (CHUNK4 * 4);
        #pragma unroll
        for (int u = 0; u < 2; u++) {
            const int v = tid + u * 128;
            if (v < CHUNK4) {
                uint4 a = buf[v];
                if (a.x | a.y | a.z | a.w) {       // exact: adj >= 0, no -0.0
                    int j = jbase + (v << 2);
                    if (a.x) { int p = atomicAdd(&s_cnt, 1); s_idx[p] = j;     s_w[p] = __uint_as_float(a.x); }
                    if (a.y) { int p = atomicAdd(&s_cnt, 1); s_idx[p] = j + 1; s_w[p] = __uint_as_float(a.y); }
                    if (a.z) { int p = atomicAdd(&s_cnt, 1); s_idx[p] = j + 2; s_w[p] = __uint_as_float(a.z); }
                    if (a.w) { int p = atomicAdd(&s_cnt, 1); s_idx[p] = j + 3; s_w[p] = __uint_as_float(a.w); }
                }
            }
        }
        __syncthreads();                     // stage st fully consumed
        if (tid == 0 && c + STAGES < NCHUNK) {
            mbar_expect_tx(smem_u32(&s_bar[st]), CHUNKB);
            bulk_g2s(smem_u32(&s_buf[st][0]),
                     arow + (size_t)(c + STAGES) * CHUNKB,
                     CHUNKB, smem_u32(&s_bar[st]));
        }
    }
    const int cnt = s_cnt;

    // ---- Pass 2: fused logits + max, then exp + sum ------------------------
    float m = -1e30f;
    for (int k = tid; k < cnt; k += 128) {
        float l = s_w[k] * __ldg(&g_score[s_idx[k]]);
        s_w[k] = l;
        m = fmaxf(m, l);
    }
    #pragma unroll
    for (int off = 16; off > 0; off >>= 1)
        m = fmaxf(m, __shfl_xor_sync(0xffffffffu, m, off));
    if (lane == 0) s_red[wid] = m;
    __syncthreads();                         // logits stored + max partials visible
    m = fmaxf(fmaxf(s_red[0], s_red[1]), fmaxf(s_red[2], s_red[3]));

    float s = 0.0f;
    for (int k = tid; k < cnt; k += 128) {
        float e = __expf(s_w[k] - m);
        s_w[k] = e;
        s += e;
    }
    #pragma unroll
    for (int off = 16; off > 0; off >>= 1)
        s += __shfl_xor_sync(0xffffffffu, s, off);
    if (lane == 0) s_red[4 + wid] = s;       // disjoint slots: no barrier needed above
    __syncthreads();
    s = s_red[4] + s_red[5] + s_red[6] + s_red[7];
    const float inv = 1.0f / s;

    // ---- Pass 3: warp-split float4 gather ----------------------------------
    const float4* inp4 = reinterpret_cast<const float4*>(inputs);
    float4 acc = make_float4(0.f, 0.f, 0.f, 0.f);
    int k = wid;
    for (; k + 12 < cnt; k += 16) {
        float w0 = s_w[k],      w1 = s_w[k + 4],  w2 = s_w[k + 8],  w3 = s_w[k + 12];
        int   j0 = s_idx[k],    j1 = s_idx[k + 4], j2 = s_idx[k + 8], j3 = s_idx[k + 12];
        float4 x0 = __ldg(&inp4[(size_t)j0 * 32 + lane]);
        float4 x1 = __ldg(&inp4[(size_t)j1 * 32 + lane]);
        float4 x2 = __ldg(&inp4[(size_t)j2 * 32 + lane]);
        float4 x3 = __ldg(&inp4[(size_t)j3 * 32 + lane]);
        acc.x += w0 * x0.x + w1 * x1.x + w2 * x2.x + w3 * x3.x;
        acc.y += w0 * x0.y + w1 * x1.y + w2 * x2.y + w3 * x3.y;
        acc.z += w0 * x0.z + w1 * x1.z + w2 * x2.z + w3 * x3.z;
        acc.w += w0 * x0.w + w1 * x1.w + w2 * x2.w + w3 * x3.w;
    }
    for (; k < cnt; k += 4) {
        float w0 = s_w[k];
        int   j0 = s_idx[k];
        float4 x0 = __ldg(&inp4[(size_t)j0 * 32 + lane]);
        acc.x += w0 * x0.x; acc.y += w0 * x0.y;
        acc.z += w0 * x0.z; acc.w += w0 * x0.w;
    }
    reinterpret_cast<float4*>(s_part)[wid * 32 + lane] = acc;
    __syncthreads();

    float v = (s_part[tid] + s_part[DD + tid] +
               s_part[2 * DD + tid] + s_part[3 * DD + tid]) * inv;
    out[(size_t)row * DD + tid] = v;
}

// ---------------------------------------------------------------------------
extern "C" void kernel_launch(void* const* d_in, const int* in_sizes, int n_in,
                              void* d_out, int out_size)
{
    const float* inputs = (const float*)d_in[0];  // [10000,128]
    const float* adj    = (const float*)d_in[1];  // [10000,10000]
    const float* Hv     = (const float*)d_in[2];  // [128,1]
    float* out          = (float*)d_out;          // [10000,128]

    score_kernel<<<(NN + 3) / 4, 128>>>(inputs, Hv);
    attn_kernel<<<NN, 128>>>(inputs, adj, out);
}